// round 16
// baseline (speedup 1.0000x reference)
#include <cuda_runtime.h>
#include <cuda_fp16.h>
#include <cuda_bf16.h>
#include <mma.h>
#include <cstdint>

using namespace nvcuda;

#define N_NODES 51200
#define N_EDGES 2048000
#define F_IN    400
#define F_HID   128
#define RO_OUT  8
#define N_GRAPHS 128
#define FC1_IN  3200
#define FC1_OUT 400
#define BN_EPS  1e-5f
#define SCAN_BLOCKS 50

// ---------------- device scratch (static, allocation-free) ----------------
__device__ __half g_h16[(size_t)N_NODES * F_HID];
__device__ __nv_bfloat16 g_w1hi[F_IN * F_HID];
__device__ __nv_bfloat16 g_w1lo[F_IN * F_HID];
__device__ __nv_bfloat16 g_w2hi[F_HID * F_HID];
__device__ __nv_bfloat16 g_w2lo[F_HID * F_HID];
__device__ __nv_bfloat16 g_a2hi[(size_t)N_NODES * F_HID];
__device__ __nv_bfloat16 g_a2lo[(size_t)N_NODES * F_HID];
__device__ unsigned long long g_dc[N_NODES];   // packed: cnt<<40 | deg*2^24
__device__ float g_dinv[N_NODES];
__device__ int   g_off[N_NODES + 1];
__device__ int   g_ptr[N_NODES];
__device__ int   g_part[SCAN_BLOCKS];
__device__ int   g_partoff[SCAN_BLOCKS];
__device__ uint2 g_edge[N_EDGES];
__device__ float g_feats[(size_t)N_NODES * RO_OUT];
__device__ float g_z[N_GRAPHS * FC1_OUT];

__device__ __forceinline__ float mishf(float x) {
    float sp = fmaxf(x, 0.0f) + log1pf(expf(-fabsf(x)));
    return x * tanhf(sp);
}

__device__ __forceinline__ void bsplit2(float a, float b,
                                        __nv_bfloat162& h, __nv_bfloat162& l) {
    h = __floats2bfloat162_rn(a, b);
    l = __floats2bfloat162_rn(a - __low2float(h), b - __high2float(h));
}

// ---------------- fp32 -> bf16 hi/lo split (weights only; tiny) ----------------
__global__ void k_split(const float4* __restrict__ src, uint4* __restrict__ hi,
                        uint4* __restrict__ lo, int n8) {
    int t = blockIdx.x * blockDim.x + threadIdx.x;
    if (t >= n8) return;
    float4 v0 = src[t * 2], v1 = src[t * 2 + 1];
    __nv_bfloat162 H[4], L[4];
    bsplit2(v0.x, v0.y, H[0], L[0]);
    bsplit2(v0.z, v0.w, H[1], L[1]);
    bsplit2(v1.x, v1.y, H[2], L[2]);
    bsplit2(v1.z, v1.w, H[3], L[3]);
    hi[t] = *reinterpret_cast<uint4*>(H);
    lo[t] = *reinterpret_cast<uint4*>(L);
}

// ---------------- graph preprocessing ----------------
__global__ void k_init_dc() {
    int i = blockIdx.x * blockDim.x + threadIdx.x;
    if (i < N_NODES) g_dc[i] = (1ull << 24);
}

__global__ void k_edge_pass1(const int* __restrict__ col, const float* __restrict__ ew) {
    int t = blockIdx.x * blockDim.x + threadIdx.x;
    int e = t * 4;
    if (e < N_EDGES) {
        int4   c4 = *reinterpret_cast<const int4*>(&col[e]);
        float4 w4 = *reinterpret_cast<const float4*>(&ew[e]);
        atomicAdd(&g_dc[c4.x], (1ull << 40) | (unsigned long long)(w4.x * 16777216.0f));
        atomicAdd(&g_dc[c4.y], (1ull << 40) | (unsigned long long)(w4.y * 16777216.0f));
        atomicAdd(&g_dc[c4.z], (1ull << 40) | (unsigned long long)(w4.z * 16777216.0f));
        atomicAdd(&g_dc[c4.w], (1ull << 40) | (unsigned long long)(w4.w * 16777216.0f));
    }
}

__global__ __launch_bounds__(1024) void k_part_dinv() {
    int b = blockIdx.x, t = threadIdx.x;
    int i = b * 1024 + t;
    unsigned long long pv = g_dc[i];
    int v = (int)(pv >> 40);
    float deg = __ull2float_rn(pv & 0xFFFFFFFFFFull) * (1.0f / 16777216.0f);
    g_dinv[i] = (deg > 0.0f) ? rsqrtf(deg) : 0.0f;
    #pragma unroll
    for (int dlt = 16; dlt > 0; dlt >>= 1) v += __shfl_down_sync(~0u, v, dlt);
    __shared__ int ws[32];
    if ((t & 31) == 0) ws[t >> 5] = v;
    __syncthreads();
    if (t < 32) {
        int x = ws[t];
        #pragma unroll
        for (int dlt = 16; dlt > 0; dlt >>= 1) x += __shfl_down_sync(~0u, x, dlt);
        if (t == 0) g_part[b] = x;
    }
}

__global__ void k_scan_part() {
    if (threadIdx.x == 0) {
        int run = 0;
        for (int b = 0; b < SCAN_BLOCKS; ++b) {
            g_partoff[b] = run;
            run += g_part[b];
        }
        g_off[N_NODES] = run;
    }
}

__global__ __launch_bounds__(1024) void k_scan_blocks() {
    int b = blockIdx.x, t = threadIdx.x;
    int i = b * 1024 + t;
    int v = (int)(g_dc[i] >> 40);
    int lane = t & 31, w = t >> 5;
    int x = v;
    #pragma unroll
    for (int dlt = 1; dlt < 32; dlt <<= 1) {
        int y = __shfl_up_sync(~0u, x, dlt);
        if (lane >= dlt) x += y;
    }
    __shared__ int ws[32];
    if (lane == 31) ws[w] = x;
    __syncthreads();
    if (w == 0) {
        int y = ws[lane];
        #pragma unroll
        for (int dlt = 1; dlt < 32; dlt <<= 1) {
            int z = __shfl_up_sync(~0u, y, dlt);
            if (lane >= dlt) y += z;
        }
        ws[lane] = y;
    }
    __syncthreads();
    int incl = x + (w > 0 ? ws[w - 1] : 0);
    int excl = incl - v + g_partoff[b];
    g_off[i] = excl;
    g_ptr[i] = excl;
}

__global__ void k_edge_pass2(const int* __restrict__ row, const int* __restrict__ col,
                             const float* __restrict__ ew) {
    int t = blockIdx.x * blockDim.x + threadIdx.x;
    int e = t * 4;
    if (e < N_EDGES) {
        int4   r4 = *reinterpret_cast<const int4*>(&row[e]);
        int4   c4 = *reinterpret_cast<const int4*>(&col[e]);
        float4 w4 = *reinterpret_cast<const float4*>(&ew[e]);
        float n0 = g_dinv[r4.x] * w4.x * g_dinv[c4.x];
        float n1 = g_dinv[r4.y] * w4.y * g_dinv[c4.y];
        float n2 = g_dinv[r4.z] * w4.z * g_dinv[c4.z];
        float n3 = g_dinv[r4.w] * w4.w * g_dinv[c4.w];
        int p0 = atomicAdd(&g_ptr[c4.x], 1);
        int p1 = atomicAdd(&g_ptr[c4.y], 1);
        int p2 = atomicAdd(&g_ptr[c4.z], 1);
        int p3 = atomicAdd(&g_ptr[c4.w], 1);
        g_edge[p0] = make_uint2((unsigned)r4.x, __float_as_uint(n0));
        g_edge[p1] = make_uint2((unsigned)r4.y, __float_as_uint(n1));
        g_edge[p2] = make_uint2((unsigned)r4.z, __float_as_uint(n2));
        g_edge[p3] = make_uint2((unsigned)r4.w, __float_as_uint(n3));
    }
}

// ---------------- 64-row double-buffered bf16-split tensor-core GEMMs ----------------
// BM=64, BN=128, BK=16; 256 threads; warp layout 2 (rows) x 4 (cols); acc[2][2]/warp
#define A_LD 24
#define B_LD 136
#define ASZ (64 * A_LD * 2)
#define BSZ (16 * B_LD * 2)
#define OF_AHI(s) ((s) * ASZ)
#define OF_ALO(s) (2 * ASZ + (s) * ASZ)
#define OF_BHI(s) (4 * ASZ + (s) * BSZ)
#define OF_BLO(s) (4 * ASZ + 2 * BSZ + (s) * BSZ)
#define SM_TOT (4 * ASZ + 4 * BSZ)

#define GEMM_COMPUTE(cur)                                                            \
    {                                                                                \
        __nv_bfloat16* Ahi_s = reinterpret_cast<__nv_bfloat16*>(smem_raw + OF_AHI(cur)); \
        __nv_bfloat16* Alo_s = reinterpret_cast<__nv_bfloat16*>(smem_raw + OF_ALO(cur)); \
        __nv_bfloat16* Bhi_s = reinterpret_cast<__nv_bfloat16*>(smem_raw + OF_BHI(cur)); \
        __nv_bfloat16* Blo_s = reinterpret_cast<__nv_bfloat16*>(smem_raw + OF_BLO(cur)); \
        wmma::fragment<wmma::matrix_b, 16, 16, 16, __nv_bfloat16, wmma::row_major> bh[2], bl[2]; \
        _Pragma("unroll")                                                            \
        for (int j = 0; j < 2; ++j) {                                                \
            wmma::load_matrix_sync(bh[j], &Bhi_s[wn * 32 + j * 16], B_LD);           \
            wmma::load_matrix_sync(bl[j], &Blo_s[wn * 32 + j * 16], B_LD);           \
        }                                                                            \
        wmma::fragment<wmma::matrix_a, 16, 16, 16, __nv_bfloat16, wmma::row_major> af[2]; \
        _Pragma("unroll")                                                            \
        for (int i = 0; i < 2; ++i)                                                  \
            wmma::load_matrix_sync(af[i], &Ahi_s[(wm * 32 + i * 16) * A_LD], A_LD);  \
        _Pragma("unroll")                                                            \
        for (int i = 0; i < 2; ++i)                                                  \
            _Pragma("unroll")                                                        \
            for (int j = 0; j < 2; ++j) {                                            \
                wmma::mma_sync(acc[i][j], af[i], bh[j], acc[i][j]);                  \
                wmma::mma_sync(acc[i][j], af[i], bl[j], acc[i][j]);                  \
            }                                                                        \
        _Pragma("unroll")                                                            \
        for (int i = 0; i < 2; ++i)                                                  \
            wmma::load_matrix_sync(af[i], &Alo_s[(wm * 32 + i * 16) * A_LD], A_LD);  \
        _Pragma("unroll")                                                            \
        for (int i = 0; i < 2; ++i)                                                  \
            _Pragma("unroll")                                                        \
            for (int j = 0; j < 2; ++j)                                              \
                wmma::mma_sync(acc[i][j], af[i], bh[j], acc[i][j]);                  \
    }

#define GEMM_EPILOGUE()                                                              \
    {                                                                                \
        float* stage = reinterpret_cast<float*>(smem_raw) + w * 16 * 20;             \
        int r = lane >> 1, c0 = (lane & 1) * 8;                                      \
        _Pragma("unroll")                                                            \
        for (int i = 0; i < 2; ++i)                                                  \
            _Pragma("unroll")                                                        \
            for (int j = 0; j < 2; ++j) {                                            \
                wmma::store_matrix_sync(stage, acc[i][j], 20, wmma::mem_row_major);  \
                __syncwarp();                                                        \
                const float* sp = stage + r * 20 + c0;                               \
                __half2 o[4];                                                        \
                _Pragma("unroll")                                                    \
                for (int q = 0; q < 4; ++q) o[q] = __floats2half2_rn(sp[2 * q], sp[2 * q + 1]); \
                size_t grow = (size_t)(row0 + wm * 32 + i * 16 + r);                 \
                int gcol = wn * 32 + j * 16 + c0;                                    \
                *reinterpret_cast<uint4*>(&C[grow * 128 + gcol]) = *reinterpret_cast<uint4*>(o); \
                __syncwarp();                                                        \
            }                                                                        \
    }

// GEMM1: A fp32 (split in-kernel), W pre-split; BM=64
__global__ __launch_bounds__(256) void k_gemm_a32(const float* __restrict__ A,
                                                  const __nv_bfloat16* __restrict__ Bhi,
                                                  const __nv_bfloat16* __restrict__ Blo,
                                                  __half* __restrict__ C, int K) {
    __shared__ __align__(16) char smem_raw[SM_TOT];
    int tid = threadIdx.x;
    int lane = tid & 31;
    int w = tid >> 5;           // 0..7
    int wm = w & 1;             // row half (32 rows)
    int wn = w >> 1;            // col quarter (32 cols)
    int row0 = blockIdx.x * 64;
    int ar = tid >> 2, ac = (tid & 3) * 4;   // A: 64x16, 4 fp32/thread
    int br = tid >> 4, bc = (tid & 15) * 8;  // B: 16x128, 8 bf16/thread

    wmma::fragment<wmma::accumulator, 16, 16, 16, float> acc[2][2];
    #pragma unroll
    for (int i = 0; i < 2; ++i)
        #pragma unroll
        for (int j = 0; j < 2; ++j) wmma::fill_fragment(acc[i][j], 0.0f);

    const float* aB = &A[(size_t)(row0 + ar) * K + ac];
    const __nv_bfloat16* bhB = &Bhi[(size_t)br * 128 + bc];
    const __nv_bfloat16* blB = &Blo[(size_t)br * 128 + bc];

    {
        float4 v = *reinterpret_cast<const float4*>(aB);
        __nv_bfloat162 H[2], L[2];
        bsplit2(v.x, v.y, H[0], L[0]);
        bsplit2(v.z, v.w, H[1], L[1]);
        *reinterpret_cast<uint2*>(smem_raw + OF_AHI(0) + (ar * A_LD + ac) * 2) = *reinterpret_cast<uint2*>(H);
        *reinterpret_cast<uint2*>(smem_raw + OF_ALO(0) + (ar * A_LD + ac) * 2) = *reinterpret_cast<uint2*>(L);
        *reinterpret_cast<uint4*>(smem_raw + OF_BHI(0) + (br * B_LD + bc) * 2) =
            *reinterpret_cast<const uint4*>(bhB);
        *reinterpret_cast<uint4*>(smem_raw + OF_BLO(0) + (br * B_LD + bc) * 2) =
            *reinterpret_cast<const uint4*>(blB);
    }
    __syncthreads();

    int nIter = K >> 4;
    for (int it = 0; it < nIter; ++it) {
        int cur = it & 1, nxt = cur ^ 1;
        bool has = (it + 1 < nIter);
        float4 v; uint4 bh4, bl4;
        if (has) {
            int k0 = (it + 1) << 4;
            v = *reinterpret_cast<const float4*>(aB + k0);
            bh4 = *reinterpret_cast<const uint4*>(bhB + (size_t)k0 * 128);
            bl4 = *reinterpret_cast<const uint4*>(blB + (size_t)k0 * 128);
        }
        GEMM_COMPUTE(cur);
        if (has) {
            __nv_bfloat162 H[2], L[2];
            bsplit2(v.x, v.y, H[0], L[0]);
            bsplit2(v.z, v.w, H[1], L[1]);
            *reinterpret_cast<uint2*>(smem_raw + OF_AHI(nxt) + (ar * A_LD + ac) * 2) = *reinterpret_cast<uint2*>(H);
            *reinterpret_cast<uint2*>(smem_raw + OF_ALO(nxt) + (ar * A_LD + ac) * 2) = *reinterpret_cast<uint2*>(L);
            *reinterpret_cast<uint4*>(smem_raw + OF_BHI(nxt) + (br * B_LD + bc) * 2) = bh4;
            *reinterpret_cast<uint4*>(smem_raw + OF_BLO(nxt) + (br * B_LD + bc) * 2) = bl4;
        }
        __syncthreads();
    }
    GEMM_EPILOGUE();
}

// GEMM2: all operands pre-split bf16; BM=64
__global__ __launch_bounds__(256) void k_gemm_ps(const __nv_bfloat16* __restrict__ Ahi,
                                                 const __nv_bfloat16* __restrict__ Alo,
                                                 const __nv_bfloat16* __restrict__ Bhi,
                                                 const __nv_bfloat16* __restrict__ Blo,
                                                 __half* __restrict__ C, int K) {
    __shared__ __align__(16) char smem_raw[SM_TOT];
    int tid = threadIdx.x;
    int lane = tid & 31;
    int w = tid >> 5;
    int wm = w & 1;
    int wn = w >> 1;
    int row0 = blockIdx.x * 64;
    int ar = tid >> 2, ac = (tid & 3) * 4;   // A: 64x16, 4 bf16/thread per buffer
    int br = tid >> 4, bc = (tid & 15) * 8;

    wmma::fragment<wmma::accumulator, 16, 16, 16, float> acc[2][2];
    #pragma unroll
    for (int i = 0; i < 2; ++i)
        #pragma unroll
        for (int j = 0; j < 2; ++j) wmma::fill_fragment(acc[i][j], 0.0f);

    const __nv_bfloat16* ahB = &Ahi[(size_t)(row0 + ar) * K + ac];
    const __nv_bfloat16* alB = &Alo[(size_t)(row0 + ar) * K + ac];
    const __nv_bfloat16* bhB = &Bhi[(size_t)br * 128 + bc];
    const __nv_bfloat16* blB = &Blo[(size_t)br * 128 + bc];

    {
        *reinterpret_cast<uint2*>(smem_raw + OF_AHI(0) + (ar * A_LD + ac) * 2) =
            *reinterpret_cast<const uint2*>(ahB);
        *reinterpret_cast<uint2*>(smem_raw + OF_ALO(0) + (ar * A_LD + ac) * 2) =
            *reinterpret_cast<const uint2*>(alB);
        *reinterpret_cast<uint4*>(smem_raw + OF_BHI(0) + (br * B_LD + bc) * 2) =
            *reinterpret_cast<const uint4*>(bhB);
        *reinterpret_cast<uint4*>(smem_raw + OF_BLO(0) + (br * B_LD + bc) * 2) =
            *reinterpret_cast<const uint4*>(blB);
    }
    __syncthreads();

    int nIter = K >> 4;
    for (int it = 0; it < nIter; ++it) {
        int cur = it & 1, nxt = cur ^ 1;
        bool has = (it + 1 < nIter);
        uint2 ah2, al2; uint4 bh4, bl4;
        if (has) {
            int k0 = (it + 1) << 4;
            ah2 = *reinterpret_cast<const uint2*>(ahB + k0);
            al2 = *reinterpret_cast<const uint2*>(alB + k0);
            bh4 = *reinterpret_cast<const uint4*>(bhB + (size_t)k0 * 128);
            bl4 = *reinterpret_cast<const uint4*>(blB + (size_t)k0 * 128);
        }
        GEMM_COMPUTE(cur);
        if (has) {
            *reinterpret_cast<uint2*>(smem_raw + OF_AHI(nxt) + (ar * A_LD + ac) * 2) = ah2;
            *reinterpret_cast<uint2*>(smem_raw + OF_ALO(nxt) + (ar * A_LD + ac) * 2) = al2;
            *reinterpret_cast<uint4*>(smem_raw + OF_BHI(nxt) + (br * B_LD + bc) * 2) = bh4;
            *reinterpret_cast<uint4*>(smem_raw + OF_BLO(nxt) + (br * B_LD + bc) * 2) = bl4;
        }
        __syncthreads();
    }
    GEMM_EPILOGUE();
}

// ---------------- agg1: 64 thr/node, emits bf16 hi/lo for GEMM2 ----------------
__global__ __launch_bounds__(64) void k_agg1(const __half2* __restrict__ hp,
                                             const float* __restrict__ bias,
                                             __nv_bfloat162* __restrict__ ahi,
                                             __nv_bfloat162* __restrict__ alo) {
    int i = blockIdx.x;
    int t = threadIdx.x;
    __shared__ uint2 s_e[64];
    float di = g_dinv[i];
    float w0 = di * di;
    float2 sv = __half22float2(hp[(size_t)i * 64 + t]);
    float a0 = w0 * sv.x, a1 = w0 * sv.y;
    int e0 = g_off[i], e1 = g_off[i + 1];
    for (int base = e0; base < e1; base += 64) {
        int n = min(64, e1 - base);
        if (t < n) s_e[t] = g_edge[base + t];
        __syncthreads();
        #pragma unroll 4
        for (int j = 0; j < n; ++j) {
            uint2 e = s_e[j];
            float nrm = __uint_as_float(e.y);
            float2 v = __half22float2(hp[(size_t)e.x * 64 + t]);
            a0 = fmaf(nrm, v.x, a0);
            a1 = fmaf(nrm, v.y, a1);
        }
        __syncthreads();
    }
    float2 bb = *reinterpret_cast<const float2*>(&bias[t * 2]);
    float ox = mishf(a0 + bb.x);
    float oy = mishf(a1 + bb.y);
    __nv_bfloat162 h, l;
    bsplit2(ox, oy, h, l);
    ahi[(size_t)i * 64 + t] = h;
    alo[(size_t)i * 64 + t] = l;
}

// ---------------- agg2 + readout fused ----------------
__global__ __launch_bounds__(64) void k_agg2ro(const __half2* __restrict__ hp,
                                               const float* __restrict__ bias,
                                               const float* __restrict__ ro_w,
                                               const float* __restrict__ ro_b) {
    int i = blockIdx.x;
    int t = threadIdx.x;
    int lane = t & 31, w = t >> 5;
    __shared__ uint2 s_e[64];
    __shared__ float pp[2][8];
    float di = g_dinv[i];
    float w0 = di * di;
    float2 sv = __half22float2(hp[(size_t)i * 64 + t]);
    float a0 = w0 * sv.x, a1 = w0 * sv.y;
    int e0 = g_off[i], e1 = g_off[i + 1];
    for (int base = e0; base < e1; base += 64) {
        int n = min(64, e1 - base);
        if (t < n) s_e[t] = g_edge[base + t];
        __syncthreads();
        #pragma unroll 4
        for (int j = 0; j < n; ++j) {
            uint2 e = s_e[j];
            float nrm = __uint_as_float(e.y);
            float2 v = __half22float2(hp[(size_t)e.x * 64 + t]);
            a0 = fmaf(nrm, v.x, a0);
            a1 = fmaf(nrm, v.y, a1);
        }
        __syncthreads();
    }
    float2 bb = *reinterpret_cast<const float2*>(&bias[t * 2]);
    float m0 = mishf(a0 + bb.x);
    float m1 = mishf(a1 + bb.y);
    const float4* wp = reinterpret_cast<const float4*>(&ro_w[t * 16]);
    float4 wa = wp[0], wb = wp[1], wc = wp[2], wd = wp[3];
    float p[8];
    p[0] = m0 * wa.x + m1 * wc.x;  p[1] = m0 * wa.y + m1 * wc.y;
    p[2] = m0 * wa.z + m1 * wc.z;  p[3] = m0 * wa.w + m1 * wc.w;
    p[4] = m0 * wb.x + m1 * wd.x;  p[5] = m0 * wb.y + m1 * wd.y;
    p[6] = m0 * wb.z + m1 * wd.z;  p[7] = m0 * wb.w + m1 * wd.w;
    #pragma unroll
    for (int j = 0; j < 8; ++j)
        #pragma unroll
        for (int d = 16; d > 0; d >>= 1)
            p[j] += __shfl_xor_sync(~0u, p[j], d);
    if (lane == 0)
        #pragma unroll
        for (int j = 0; j < 8; ++j) pp[w][j] = p[j];
    __syncthreads();
    if (t < 8)
        g_feats[(size_t)i * 8 + t] = mishf(pp[0][t] + pp[1][t] + __ldg(&ro_b[t]));
}

// ---------------- fc1: 2 graphs per block (smem feats) ----------------
__global__ __launch_bounds__(400) void k_fc1(const float* __restrict__ W,
                                             const float* __restrict__ b) {
    int g0 = blockIdx.x * 2;
    int c = threadIdx.x;
    __shared__ float s0[FC1_IN], s1[FC1_IN];
    for (int k = c; k < FC1_IN; k += FC1_OUT) {
        s0[k] = g_feats[(size_t)g0 * FC1_IN + k];
        s1[k] = g_feats[(size_t)(g0 + 1) * FC1_IN + k];
    }
    __syncthreads();
    float a0 = b[c], a1 = a0;
    #pragma unroll 4
    for (int k = 0; k < FC1_IN; ++k) {
        float w = W[(size_t)k * FC1_OUT + c];
        a0 = fmaf(s0[k], w, a0);
        a1 = fmaf(s1[k], w, a1);
    }
    g_z[g0 * FC1_OUT + c] = a0;
    g_z[(g0 + 1) * FC1_OUT + c] = a1;
}

// ---------------- head: bn stats (per-block, redundant) + mish + fc2 ----------------
__global__ __launch_bounds__(512) void k_head(const float* __restrict__ gamma,
                                              const float* __restrict__ beta,
                                              const float* __restrict__ w2,
                                              const float* __restrict__ b2,
                                              float* __restrict__ out) {
    int g = blockIdx.x;
    int t = threadIdx.x;
    __shared__ float s0[512], s1[512];
    float v0 = 0.0f, v1 = 0.0f;
    if (t < FC1_OUT) {
        float s = 0.0f;
        #pragma unroll 4
        for (int r = 0; r < N_GRAPHS; ++r) s += g_z[r * FC1_OUT + t];
        float mu = s * (1.0f / N_GRAPHS);
        float var = 0.0f;
        #pragma unroll 4
        for (int r = 0; r < N_GRAPHS; ++r) {
            float d = g_z[r * FC1_OUT + t] - mu;
            var = fmaf(d, d, var);
        }
        float rstd = rsqrtf(var * (1.0f / N_GRAPHS) + BN_EPS);
        float zn = (g_z[g * FC1_OUT + t] - mu) * rstd * gamma[t] + beta[t];
        float m = mishf(zn);
        v0 = m * w2[t * 2 + 0];
        v1 = m * w2[t * 2 + 1];
    }
    s0[t] = v0; s1[t] = v1;
    __syncthreads();
    for (int d = 256; d > 0; d >>= 1) {
        if (t < d) { s0[t] += s0[t + d]; s1[t] += s1[t + d]; }
        __syncthreads();
    }
    if (t == 0) {
        out[g * 2 + 0] = s0[0] + b2[0];
        out[g * 2 + 1] = s1[0] + b2[1];
    }
}

// ---------------- host launcher ----------------
extern "C" void kernel_launch(void* const* d_in, const int* in_sizes, int n_in,
                              void* d_out, int out_size) {
    const float* x      = (const float*)d_in[0];
    const int*   ei     = (const int*)d_in[1];
    const float* ea     = (const float*)d_in[2];
    const float* w1     = (const float*)d_in[4];
    const float* b1     = (const float*)d_in[5];
    const float* w2     = (const float*)d_in[6];
    const float* b2     = (const float*)d_in[7];
    const float* ro_w   = (const float*)d_in[8];
    const float* ro_b   = (const float*)d_in[9];
    const float* fc1_w  = (const float*)d_in[10];
    const float* fc1_b  = (const float*)d_in[11];
    const float* gamma  = (const float*)d_in[12];
    const float* beta   = (const float*)d_in[13];
    const float* fc2_w  = (const float*)d_in[14];
    const float* fc2_b  = (const float*)d_in[15];
    float* out = (float*)d_out;

    const int* row = ei;
    const int* col = ei + N_EDGES;

    __half* pH = nullptr;
    __nv_bfloat16 *pw1hi, *pw1lo, *pw2hi, *pw2lo, *pa2hi, *pa2lo;
    cudaGetSymbolAddress((void**)&pH, g_h16);
    cudaGetSymbolAddress((void**)&pw1hi, g_w1hi);
    cudaGetSymbolAddress((void**)&pw1lo, g_w1lo);
    cudaGetSymbolAddress((void**)&pw2hi, g_w2hi);
    cudaGetSymbolAddress((void**)&pw2lo, g_w2lo);
    cudaGetSymbolAddress((void**)&pa2hi, g_a2hi);
    cudaGetSymbolAddress((void**)&pa2lo, g_a2lo);
    __half2* pH2 = reinterpret_cast<__half2*>(pH);

    static cudaStream_t s2 = nullptr;
    static cudaEvent_t evFork = nullptr, evJoin = nullptr;
    if (!s2) {
        cudaStreamCreateWithFlags(&s2, cudaStreamNonBlocking);
        cudaEventCreateWithFlags(&evFork, cudaEventDisableTiming);
        cudaEventCreateWithFlags(&evJoin, cudaEventDisableTiming);
    }

    cudaEventRecord(evFork, 0);
    cudaStreamWaitEvent(s2, evFork, 0);

    k_split<<<25, 256>>>((const float4*)w1, (uint4*)pw1hi, (uint4*)pw1lo,
                         F_IN * F_HID / 8);
    k_split<<<8, 256>>>((const float4*)w2, (uint4*)pw2hi, (uint4*)pw2lo,
                        F_HID * F_HID / 8);
    k_init_dc<<<(N_NODES + 255) / 256, 256, 0, s2>>>();
    k_gemm_a32<<<N_NODES / 64, 256>>>(x, pw1hi, pw1lo, pH, F_IN);
    k_edge_pass1<<<(N_EDGES / 4 + 255) / 256, 256, 0, s2>>>(col, ea);
    k_part_dinv<<<SCAN_BLOCKS, 1024, 0, s2>>>();
    k_scan_part<<<1, 32, 0, s2>>>();
    k_scan_blocks<<<SCAN_BLOCKS, 1024, 0, s2>>>();
    k_edge_pass2<<<(N_EDGES / 4 + 255) / 256, 256, 0, s2>>>(row, col, ea);
    cudaEventRecord(evJoin, s2);

    cudaStreamWaitEvent(0, evJoin, 0);

    k_agg1<<<N_NODES, 64>>>(pH2, b1, (__nv_bfloat162*)pa2hi, (__nv_bfloat162*)pa2lo);
    k_gemm_ps<<<N_NODES / 64, 256>>>(pa2hi, pa2lo, pw2hi, pw2lo, pH, F_HID);
    k_agg2ro<<<N_NODES, 64>>>(pH2, b2, ro_w, ro_b);

    k_fc1<<<N_GRAPHS / 2, FC1_OUT>>>(fc1_w, fc1_b);
    k_head<<<N_GRAPHS, 512>>>(gamma, beta, fc2_w, fc2_b, out);
}

// round 17
// speedup vs baseline: 1.5493x; 1.5493x over previous
#include <cuda_runtime.h>
#include <cuda_fp16.h>
#include <cuda_bf16.h>
#include <mma.h>
#include <cstdint>

using namespace nvcuda;

#define N_NODES 51200
#define N_EDGES 2048000
#define F_IN    400
#define F_HID   128
#define RO_OUT  8
#define N_GRAPHS 128
#define FC1_IN  3200
#define FC1_OUT 400
#define KCHUNK  800
#define NCHUNKS 4
#define BN_EPS  1e-5f
#define SCAN_BLOCKS 50

// ---------------- device scratch (static, allocation-free) ----------------
__device__ __half g_h16[(size_t)N_NODES * F_HID];
__device__ __nv_bfloat16 g_w1hi[F_IN * F_HID];
__device__ __nv_bfloat16 g_w1lo[F_IN * F_HID];
__device__ __nv_bfloat16 g_w2hi[F_HID * F_HID];
__device__ __nv_bfloat16 g_w2lo[F_HID * F_HID];
__device__ __nv_bfloat16 g_a2hi[(size_t)N_NODES * F_HID];
__device__ __nv_bfloat16 g_a2lo[(size_t)N_NODES * F_HID];
__device__ unsigned long long g_dc[N_NODES];
__device__ float g_dinv[N_NODES];
__device__ int   g_off[N_NODES + 1];
__device__ int   g_ptr[N_NODES];
__device__ int   g_part[SCAN_BLOCKS];
__device__ int   g_partoff[SCAN_BLOCKS];
__device__ uint2 g_edge[N_EDGES];
__device__ float g_feats[(size_t)N_NODES * RO_OUT];
__device__ float g_zp[NCHUNKS * N_GRAPHS * FC1_OUT];
__device__ float g_z[N_GRAPHS * FC1_OUT];

__device__ __forceinline__ float mishf(float x) {
    float sp = fmaxf(x, 0.0f) + log1pf(expf(-fabsf(x)));
    return x * tanhf(sp);
}

__device__ __forceinline__ void bsplit2(float a, float b,
                                        __nv_bfloat162& h, __nv_bfloat162& l) {
    h = __floats2bfloat162_rn(a, b);
    l = __floats2bfloat162_rn(a - __low2float(h), b - __high2float(h));
}

// ---------------- fp32 -> bf16 hi/lo split (weights only; tiny) ----------------
__global__ void k_split(const float4* __restrict__ src, uint4* __restrict__ hi,
                        uint4* __restrict__ lo, int n8) {
    int t = blockIdx.x * blockDim.x + threadIdx.x;
    if (t >= n8) return;
    float4 v0 = src[t * 2], v1 = src[t * 2 + 1];
    __nv_bfloat162 H[4], L[4];
    bsplit2(v0.x, v0.y, H[0], L[0]);
    bsplit2(v0.z, v0.w, H[1], L[1]);
    bsplit2(v1.x, v1.y, H[2], L[2]);
    bsplit2(v1.z, v1.w, H[3], L[3]);
    hi[t] = *reinterpret_cast<uint4*>(H);
    lo[t] = *reinterpret_cast<uint4*>(L);
}

// ---------------- graph preprocessing ----------------
__global__ void k_init_dc() {
    int i = blockIdx.x * blockDim.x + threadIdx.x;
    if (i < N_NODES) g_dc[i] = (1ull << 24);
}

__global__ void k_edge_pass1(const int* __restrict__ col, const float* __restrict__ ew) {
    int t = blockIdx.x * blockDim.x + threadIdx.x;
    int e = t * 4;
    if (e < N_EDGES) {
        int4   c4 = *reinterpret_cast<const int4*>(&col[e]);
        float4 w4 = *reinterpret_cast<const float4*>(&ew[e]);
        atomicAdd(&g_dc[c4.x], (1ull << 40) | (unsigned long long)(w4.x * 16777216.0f));
        atomicAdd(&g_dc[c4.y], (1ull << 40) | (unsigned long long)(w4.y * 16777216.0f));
        atomicAdd(&g_dc[c4.z], (1ull << 40) | (unsigned long long)(w4.z * 16777216.0f));
        atomicAdd(&g_dc[c4.w], (1ull << 40) | (unsigned long long)(w4.w * 16777216.0f));
    }
}

__global__ __launch_bounds__(1024) void k_part_dinv() {
    int b = blockIdx.x, t = threadIdx.x;
    int i = b * 1024 + t;
    unsigned long long pv = g_dc[i];
    int v = (int)(pv >> 40);
    float deg = __ull2float_rn(pv & 0xFFFFFFFFFFull) * (1.0f / 16777216.0f);
    g_dinv[i] = (deg > 0.0f) ? rsqrtf(deg) : 0.0f;
    #pragma unroll
    for (int dlt = 16; dlt > 0; dlt >>= 1) v += __shfl_down_sync(~0u, v, dlt);
    __shared__ int ws[32];
    if ((t & 31) == 0) ws[t >> 5] = v;
    __syncthreads();
    if (t < 32) {
        int x = ws[t];
        #pragma unroll
        for (int dlt = 16; dlt > 0; dlt >>= 1) x += __shfl_down_sync(~0u, x, dlt);
        if (t == 0) g_part[b] = x;
    }
}

__global__ void k_scan_part() {
    if (threadIdx.x == 0) {
        int run = 0;
        for (int b = 0; b < SCAN_BLOCKS; ++b) {
            g_partoff[b] = run;
            run += g_part[b];
        }
        g_off[N_NODES] = run;
    }
}

__global__ __launch_bounds__(1024) void k_scan_blocks() {
    int b = blockIdx.x, t = threadIdx.x;
    int i = b * 1024 + t;
    int v = (int)(g_dc[i] >> 40);
    int lane = t & 31, w = t >> 5;
    int x = v;
    #pragma unroll
    for (int dlt = 1; dlt < 32; dlt <<= 1) {
        int y = __shfl_up_sync(~0u, x, dlt);
        if (lane >= dlt) x += y;
    }
    __shared__ int ws[32];
    if (lane == 31) ws[w] = x;
    __syncthreads();
    if (w == 0) {
        int y = ws[lane];
        #pragma unroll
        for (int dlt = 1; dlt < 32; dlt <<= 1) {
            int z = __shfl_up_sync(~0u, y, dlt);
            if (lane >= dlt) y += z;
        }
        ws[lane] = y;
    }
    __syncthreads();
    int incl = x + (w > 0 ? ws[w - 1] : 0);
    int excl = incl - v + g_partoff[b];
    g_off[i] = excl;
    g_ptr[i] = excl;
}

__global__ void k_edge_pass2(const int* __restrict__ row, const int* __restrict__ col,
                             const float* __restrict__ ew) {
    int t = blockIdx.x * blockDim.x + threadIdx.x;
    int e = t * 4;
    if (e < N_EDGES) {
        int4   r4 = *reinterpret_cast<const int4*>(&row[e]);
        int4   c4 = *reinterpret_cast<const int4*>(&col[e]);
        float4 w4 = *reinterpret_cast<const float4*>(&ew[e]);
        float n0 = g_dinv[r4.x] * w4.x * g_dinv[c4.x];
        float n1 = g_dinv[r4.y] * w4.y * g_dinv[c4.y];
        float n2 = g_dinv[r4.z] * w4.z * g_dinv[c4.z];
        float n3 = g_dinv[r4.w] * w4.w * g_dinv[c4.w];
        int p0 = atomicAdd(&g_ptr[c4.x], 1);
        int p1 = atomicAdd(&g_ptr[c4.y], 1);
        int p2 = atomicAdd(&g_ptr[c4.z], 1);
        int p3 = atomicAdd(&g_ptr[c4.w], 1);
        g_edge[p0] = make_uint2((unsigned)r4.x, __float_as_uint(n0));
        g_edge[p1] = make_uint2((unsigned)r4.y, __float_as_uint(n1));
        g_edge[p2] = make_uint2((unsigned)r4.z, __float_as_uint(n2));
        g_edge[p3] = make_uint2((unsigned)r4.w, __float_as_uint(n3));
    }
}

// ---------------- 128-row double-buffered bf16-split tensor-core GEMMs ----------------
#define A_LD 24
#define B_LD 136
#define ASZ (128 * A_LD * 2)
#define BSZ (16 * B_LD * 2)
#define OF_AHI(s) ((s) * ASZ)
#define OF_ALO(s) (2 * ASZ + (s) * ASZ)
#define OF_BHI(s) (4 * ASZ + (s) * BSZ)
#define OF_BLO(s) (4 * ASZ + 2 * BSZ + (s) * BSZ)
#define SM_TOT (4 * ASZ + 4 * BSZ)

#define GEMM_COMPUTE(cur)                                                            \
    {                                                                                \
        __nv_bfloat16* Ahi_s = reinterpret_cast<__nv_bfloat16*>(smem_raw + OF_AHI(cur)); \
        __nv_bfloat16* Alo_s = reinterpret_cast<__nv_bfloat16*>(smem_raw + OF_ALO(cur)); \
        __nv_bfloat16* Bhi_s = reinterpret_cast<__nv_bfloat16*>(smem_raw + OF_BHI(cur)); \
        __nv_bfloat16* Blo_s = reinterpret_cast<__nv_bfloat16*>(smem_raw + OF_BLO(cur)); \
        wmma::fragment<wmma::matrix_b, 16, 16, 16, __nv_bfloat16, wmma::row_major> bh[2], bl[2]; \
        _Pragma("unroll")                                                            \
        for (int j = 0; j < 2; ++j) {                                                \
            wmma::load_matrix_sync(bh[j], &Bhi_s[wn * 32 + j * 16], B_LD);           \
            wmma::load_matrix_sync(bl[j], &Blo_s[wn * 32 + j * 16], B_LD);           \
        }                                                                            \
        wmma::fragment<wmma::matrix_a, 16, 16, 16, __nv_bfloat16, wmma::row_major> af[4]; \
        _Pragma("unroll")                                                            \
        for (int i = 0; i < 4; ++i)                                                  \
            wmma::load_matrix_sync(af[i], &Ahi_s[(wm * 64 + i * 16) * A_LD], A_LD);  \
        _Pragma("unroll")                                                            \
        for (int i = 0; i < 4; ++i)                                                  \
            _Pragma("unroll")                                                        \
            for (int j = 0; j < 2; ++j) {                                            \
                wmma::mma_sync(acc[i][j], af[i], bh[j], acc[i][j]);                  \
                wmma::mma_sync(acc[i][j], af[i], bl[j], acc[i][j]);                  \
            }                                                                        \
        _Pragma("unroll")                                                            \
        for (int i = 0; i < 4; ++i)                                                  \
            wmma::load_matrix_sync(af[i], &Alo_s[(wm * 64 + i * 16) * A_LD], A_LD);  \
        _Pragma("unroll")                                                            \
        for (int i = 0; i < 4; ++i)                                                  \
            _Pragma("unroll")                                                        \
            for (int j = 0; j < 2; ++j)                                              \
                wmma::mma_sync(acc[i][j], af[i], bh[j], acc[i][j]);                  \
    }

#define GEMM_EPILOGUE()                                                              \
    {                                                                                \
        float* stage = reinterpret_cast<float*>(smem_raw) + w * 16 * 20;             \
        int r = lane >> 1, c0 = (lane & 1) * 8;                                      \
        _Pragma("unroll")                                                            \
        for (int i = 0; i < 4; ++i)                                                  \
            _Pragma("unroll")                                                        \
            for (int j = 0; j < 2; ++j) {                                            \
                wmma::store_matrix_sync(stage, acc[i][j], 20, wmma::mem_row_major);  \
                __syncwarp();                                                        \
                const float* sp = stage + r * 20 + c0;                               \
                __half2 o[4];                                                        \
                _Pragma("unroll")                                                    \
                for (int q = 0; q < 4; ++q) o[q] = __floats2half2_rn(sp[2 * q], sp[2 * q + 1]); \
                size_t grow = (size_t)(row0 + wm * 64 + i * 16 + r);                 \
                int gcol = wn * 32 + j * 16 + c0;                                    \
                *reinterpret_cast<uint4*>(&C[grow * 128 + gcol]) = *reinterpret_cast<uint4*>(o); \
                __syncwarp();                                                        \
            }                                                                        \
    }

__global__ __launch_bounds__(256) void k_gemm_a32(const float* __restrict__ A,
                                                  const __nv_bfloat16* __restrict__ Bhi,
                                                  const __nv_bfloat16* __restrict__ Blo,
                                                  __half* __restrict__ C, int K) {
    __shared__ __align__(16) char smem_raw[SM_TOT];
    int tid = threadIdx.x;
    int lane = tid & 31;
    int w = tid >> 5;
    int wm = w & 1;
    int wn = w >> 1;
    int row0 = blockIdx.x * 128;
    int ar = tid >> 1, ac = (tid & 1) * 8;
    int br = tid >> 4, bc = (tid & 15) * 8;

    wmma::fragment<wmma::accumulator, 16, 16, 16, float> acc[4][2];
    #pragma unroll
    for (int i = 0; i < 4; ++i)
        #pragma unroll
        for (int j = 0; j < 2; ++j) wmma::fill_fragment(acc[i][j], 0.0f);

    const float* aB = &A[(size_t)(row0 + ar) * K + ac];
    const __nv_bfloat16* bhB = &Bhi[(size_t)br * 128 + bc];
    const __nv_bfloat16* blB = &Blo[(size_t)br * 128 + bc];

    {
        float4 v0 = *reinterpret_cast<const float4*>(aB);
        float4 v1 = *reinterpret_cast<const float4*>(aB + 4);
        __nv_bfloat162 H[4], L[4];
        bsplit2(v0.x, v0.y, H[0], L[0]);
        bsplit2(v0.z, v0.w, H[1], L[1]);
        bsplit2(v1.x, v1.y, H[2], L[2]);
        bsplit2(v1.z, v1.w, H[3], L[3]);
        *reinterpret_cast<uint4*>(smem_raw + OF_AHI(0) + (ar * A_LD + ac) * 2) = *reinterpret_cast<uint4*>(H);
        *reinterpret_cast<uint4*>(smem_raw + OF_ALO(0) + (ar * A_LD + ac) * 2) = *reinterpret_cast<uint4*>(L);
        *reinterpret_cast<uint4*>(smem_raw + OF_BHI(0) + (br * B_LD + bc) * 2) =
            *reinterpret_cast<const uint4*>(bhB);
        *reinterpret_cast<uint4*>(smem_raw + OF_BLO(0) + (br * B_LD + bc) * 2) =
            *reinterpret_cast<const uint4*>(blB);
    }
    __syncthreads();

    int nIter = K >> 4;
    for (int it = 0; it < nIter; ++it) {
        int cur = it & 1, nxt = cur ^ 1;
        bool has = (it + 1 < nIter);
        float4 v0, v1; uint4 bh4, bl4;
        if (has) {
            int k0 = (it + 1) << 4;
            v0 = *reinterpret_cast<const float4*>(aB + k0);
            v1 = *reinterpret_cast<const float4*>(aB + k0 + 4);
            bh4 = *reinterpret_cast<const uint4*>(bhB + (size_t)k0 * 128);
            bl4 = *reinterpret_cast<const uint4*>(blB + (size_t)k0 * 128);
        }
        GEMM_COMPUTE(cur);
        if (has) {
            __nv_bfloat162 H[4], L[4];
            bsplit2(v0.x, v0.y, H[0], L[0]);
            bsplit2(v0.z, v0.w, H[1], L[1]);
            bsplit2(v1.x, v1.y, H[2], L[2]);
            bsplit2(v1.z, v1.w, H[3], L[3]);
            *reinterpret_cast<uint4*>(smem_raw + OF_AHI(nxt) + (ar * A_LD + ac) * 2) = *reinterpret_cast<uint4*>(H);
            *reinterpret_cast<uint4*>(smem_raw + OF_ALO(nxt) + (ar * A_LD + ac) * 2) = *reinterpret_cast<uint4*>(L);
            *reinterpret_cast<uint4*>(smem_raw + OF_BHI(nxt) + (br * B_LD + bc) * 2) = bh4;
            *reinterpret_cast<uint4*>(smem_raw + OF_BLO(nxt) + (br * B_LD + bc) * 2) = bl4;
        }
        __syncthreads();
    }
    GEMM_EPILOGUE();
}

__global__ __launch_bounds__(256) void k_gemm_ps(const __nv_bfloat16* __restrict__ Ahi,
                                                 const __nv_bfloat16* __restrict__ Alo,
                                                 const __nv_bfloat16* __restrict__ Bhi,
                                                 const __nv_bfloat16* __restrict__ Blo,
                                                 __half* __restrict__ C, int K) {
    __shared__ __align__(16) char smem_raw[SM_TOT];
    int tid = threadIdx.x;
    int lane = tid & 31;
    int w = tid >> 5;
    int wm = w & 1;
    int wn = w >> 1;
    int row0 = blockIdx.x * 128;
    int ar = tid >> 1, ac = (tid & 1) * 8;
    int br = tid >> 4, bc = (tid & 15) * 8;

    wmma::fragment<wmma::accumulator, 16, 16, 16, float> acc[4][2];
    #pragma unroll
    for (int i = 0; i < 4; ++i)
        #pragma unroll
        for (int j = 0; j < 2; ++j) wmma::fill_fragment(acc[i][j], 0.0f);

    const __nv_bfloat16* ahB = &Ahi[(size_t)(row0 + ar) * K + ac];
    const __nv_bfloat16* alB = &Alo[(size_t)(row0 + ar) * K + ac];
    const __nv_bfloat16* bhB = &Bhi[(size_t)br * 128 + bc];
    const __nv_bfloat16* blB = &Blo[(size_t)br * 128 + bc];

    {
        *reinterpret_cast<uint4*>(smem_raw + OF_AHI(0) + (ar * A_LD + ac) * 2) =
            *reinterpret_cast<const uint4*>(ahB);
        *reinterpret_cast<uint4*>(smem_raw + OF_ALO(0) + (ar * A_LD + ac) * 2) =
            *reinterpret_cast<const uint4*>(alB);
        *reinterpret_cast<uint4*>(smem_raw + OF_BHI(0) + (br * B_LD + bc) * 2) =
            *reinterpret_cast<const uint4*>(bhB);
        *reinterpret_cast<uint4*>(smem_raw + OF_BLO(0) + (br * B_LD + bc) * 2) =
            *reinterpret_cast<const uint4*>(blB);
    }
    __syncthreads();

    int nIter = K >> 4;
    for (int it = 0; it < nIter; ++it) {
        int cur = it & 1, nxt = cur ^ 1;
        bool has = (it + 1 < nIter);
        uint4 ah4, al4, bh4, bl4;
        if (has) {
            int k0 = (it + 1) << 4;
            ah4 = *reinterpret_cast<const uint4*>(ahB + k0);
            al4 = *reinterpret_cast<const uint4*>(alB + k0);
            bh4 = *reinterpret_cast<const uint4*>(bhB + (size_t)k0 * 128);
            bl4 = *reinterpret_cast<const uint4*>(blB + (size_t)k0 * 128);
        }
        GEMM_COMPUTE(cur);
        if (has) {
            *reinterpret_cast<uint4*>(smem_raw + OF_AHI(nxt) + (ar * A_LD + ac) * 2) = ah4;
            *reinterpret_cast<uint4*>(smem_raw + OF_ALO(nxt) + (ar * A_LD + ac) * 2) = al4;
            *reinterpret_cast<uint4*>(smem_raw + OF_BHI(nxt) + (br * B_LD + bc) * 2) = bh4;
            *reinterpret_cast<uint4*>(smem_raw + OF_BLO(nxt) + (br * B_LD + bc) * 2) = bl4;
        }
        __syncthreads();
    }
    GEMM_EPILOGUE();
}

// ---------------- agg1: 64 thr/node, emits bf16 hi/lo for GEMM2 ----------------
__global__ __launch_bounds__(64) void k_agg1(const __half2* __restrict__ hp,
                                             const float* __restrict__ bias,
                                             __nv_bfloat162* __restrict__ ahi,
                                             __nv_bfloat162* __restrict__ alo) {
    int i = blockIdx.x;
    int t = threadIdx.x;
    __shared__ uint2 s_e[64];
    float di = g_dinv[i];
    float w0 = di * di;
    float2 sv = __half22float2(hp[(size_t)i * 64 + t]);
    float a0 = w0 * sv.x, a1 = w0 * sv.y;
    int e0 = g_off[i], e1 = g_off[i + 1];
    for (int base = e0; base < e1; base += 64) {
        int n = min(64, e1 - base);
        if (t < n) s_e[t] = g_edge[base + t];
        __syncthreads();
        #pragma unroll 4
        for (int j = 0; j < n; ++j) {
            uint2 e = s_e[j];
            float nrm = __uint_as_float(e.y);
            float2 v = __half22float2(hp[(size_t)e.x * 64 + t]);
            a0 = fmaf(nrm, v.x, a0);
            a1 = fmaf(nrm, v.y, a1);
        }
        __syncthreads();
    }
    float2 bb = *reinterpret_cast<const float2*>(&bias[t * 2]);
    float ox = mishf(a0 + bb.x);
    float oy = mishf(a1 + bb.y);
    __nv_bfloat162 h, l;
    bsplit2(ox, oy, h, l);
    ahi[(size_t)i * 64 + t] = h;
    alo[(size_t)i * 64 + t] = l;
}

// ---------------- agg2 + readout fused ----------------
__global__ __launch_bounds__(64) void k_agg2ro(const __half2* __restrict__ hp,
                                               const float* __restrict__ bias,
                                               const float* __restrict__ ro_w,
                                               const float* __restrict__ ro_b) {
    int i = blockIdx.x;
    int t = threadIdx.x;
    int lane = t & 31, w = t >> 5;
    __shared__ uint2 s_e[64];
    __shared__ float pp[2][8];
    float di = g_dinv[i];
    float w0 = di * di;
    float2 sv = __half22float2(hp[(size_t)i * 64 + t]);
    float a0 = w0 * sv.x, a1 = w0 * sv.y;
    int e0 = g_off[i], e1 = g_off[i + 1];
    for (int base = e0; base < e1; base += 64) {
        int n = min(64, e1 - base);
        if (t < n) s_e[t] = g_edge[base + t];
        __syncthreads();
        #pragma unroll 4
        for (int j = 0; j < n; ++j) {
            uint2 e = s_e[j];
            float nrm = __uint_as_float(e.y);
            float2 v = __half22float2(hp[(size_t)e.x * 64 + t]);
            a0 = fmaf(nrm, v.x, a0);
            a1 = fmaf(nrm, v.y, a1);
        }
        __syncthreads();
    }
    float2 bb = *reinterpret_cast<const float2*>(&bias[t * 2]);
    float m0 = mishf(a0 + bb.x);
    float m1 = mishf(a1 + bb.y);
    const float4* wp = reinterpret_cast<const float4*>(&ro_w[t * 16]);
    float4 wa = wp[0], wb = wp[1], wc = wp[2], wd = wp[3];
    float p[8];
    p[0] = m0 * wa.x + m1 * wc.x;  p[1] = m0 * wa.y + m1 * wc.y;
    p[2] = m0 * wa.z + m1 * wc.z;  p[3] = m0 * wa.w + m1 * wc.w;
    p[4] = m0 * wb.x + m1 * wd.x;  p[5] = m0 * wb.y + m1 * wd.y;
    p[6] = m0 * wb.z + m1 * wd.z;  p[7] = m0 * wb.w + m1 * wd.w;
    #pragma unroll
    for (int j = 0; j < 8; ++j)
        #pragma unroll
        for (int d = 16; d > 0; d >>= 1)
            p[j] += __shfl_xor_sync(~0u, p[j], d);
    if (lane == 0)
        #pragma unroll
        for (int j = 0; j < 8; ++j) pp[w][j] = p[j];
    __syncthreads();
    if (t < 8)
        g_feats[(size_t)i * 8 + t] = mishf(pp[0][t] + pp[1][t] + __ldg(&ro_b[t]));
}

// ---------------- fc1: k-split x4, 1 graph per block, MLP-8 inner loop ----------------
__global__ __launch_bounds__(400) void k_fc1(const float* __restrict__ W) {
    int g = blockIdx.x >> 2;        // graph
    int q = blockIdx.x & 3;         // k-chunk
    int c = threadIdx.x;            // 0..399
    __shared__ float s[KCHUNK];
    int kbase = q * KCHUNK;
    for (int k = c; k < KCHUNK; k += FC1_OUT)
        s[k] = g_feats[(size_t)g * FC1_IN + kbase + k];
    __syncthreads();
    const float* Wp = W + (size_t)kbase * FC1_OUT + c;
    float acc = 0.0f;
    for (int k = 0; k < KCHUNK; k += 8) {
        float w0 = Wp[(size_t)(k + 0) * FC1_OUT];
        float w1 = Wp[(size_t)(k + 1) * FC1_OUT];
        float w2 = Wp[(size_t)(k + 2) * FC1_OUT];
        float w3 = Wp[(size_t)(k + 3) * FC1_OUT];
        float w4 = Wp[(size_t)(k + 4) * FC1_OUT];
        float w5 = Wp[(size_t)(k + 5) * FC1_OUT];
        float w6 = Wp[(size_t)(k + 6) * FC1_OUT];
        float w7 = Wp[(size_t)(k + 7) * FC1_OUT];
        acc = fmaf(s[k + 0], w0, acc);
        acc = fmaf(s[k + 1], w1, acc);
        acc = fmaf(s[k + 2], w2, acc);
        acc = fmaf(s[k + 3], w3, acc);
        acc = fmaf(s[k + 4], w4, acc);
        acc = fmaf(s[k + 5], w5, acc);
        acc = fmaf(s[k + 6], w6, acc);
        acc = fmaf(s[k + 7], w7, acc);
    }
    g_zp[(q * N_GRAPHS + g) * FC1_OUT + c] = acc;
}

// ---------------- combine fc1 partials + bias ----------------
__global__ void k_zred(const float* __restrict__ b) {
    int i = blockIdx.x * blockDim.x + threadIdx.x;
    if (i >= N_GRAPHS * FC1_OUT) return;
    int c = i % FC1_OUT;
    g_z[i] = g_zp[i] + g_zp[N_GRAPHS * FC1_OUT + i]
           + g_zp[2 * N_GRAPHS * FC1_OUT + i] + g_zp[3 * N_GRAPHS * FC1_OUT + i]
           + b[c];
}

// ---------------- head: bn stats (per-block, redundant) + mish + fc2 ----------------
__global__ __launch_bounds__(512) void k_head(const float* __restrict__ gamma,
                                              const float* __restrict__ beta,
                                              const float* __restrict__ w2,
                                              const float* __restrict__ b2,
                                              float* __restrict__ out) {
    int g = blockIdx.x;
    int t = threadIdx.x;
    __shared__ float s0[512], s1[512];
    float v0 = 0.0f, v1 = 0.0f;
    if (t < FC1_OUT) {
        float s = 0.0f;
        #pragma unroll 4
        for (int r = 0; r < N_GRAPHS; ++r) s += g_z[r * FC1_OUT + t];
        float mu = s * (1.0f / N_GRAPHS);
        float var = 0.0f;
        #pragma unroll 4
        for (int r = 0; r < N_GRAPHS; ++r) {
            float d = g_z[r * FC1_OUT + t] - mu;
            var = fmaf(d, d, var);
        }
        float rstd = rsqrtf(var * (1.0f / N_GRAPHS) + BN_EPS);
        float zn = (g_z[g * FC1_OUT + t] - mu) * rstd * gamma[t] + beta[t];
        float m = mishf(zn);
        v0 = m * w2[t * 2 + 0];
        v1 = m * w2[t * 2 + 1];
    }
    s0[t] = v0; s1[t] = v1;
    __syncthreads();
    for (int d = 256; d > 0; d >>= 1) {
        if (t < d) { s0[t] += s0[t + d]; s1[t] += s1[t + d]; }
        __syncthreads();
    }
    if (t == 0) {
        out[g * 2 + 0] = s0[0] + b2[0];
        out[g * 2 + 1] = s1[0] + b2[1];
    }
}

// ---------------- host launcher ----------------
extern "C" void kernel_launch(void* const* d_in, const int* in_sizes, int n_in,
                              void* d_out, int out_size) {
    const float* x      = (const float*)d_in[0];
    const int*   ei     = (const int*)d_in[1];
    const float* ea     = (const float*)d_in[2];
    const float* w1     = (const float*)d_in[4];
    const float* b1     = (const float*)d_in[5];
    const float* w2     = (const float*)d_in[6];
    const float* b2     = (const float*)d_in[7];
    const float* ro_w   = (const float*)d_in[8];
    const float* ro_b   = (const float*)d_in[9];
    const float* fc1_w  = (const float*)d_in[10];
    const float* fc1_b  = (const float*)d_in[11];
    const float* gamma  = (const float*)d_in[12];
    const float* beta   = (const float*)d_in[13];
    const float* fc2_w  = (const float*)d_in[14];
    const float* fc2_b  = (const float*)d_in[15];
    float* out = (float*)d_out;

    const int* row = ei;
    const int* col = ei + N_EDGES;

    __half* pH = nullptr;
    __nv_bfloat16 *pw1hi, *pw1lo, *pw2hi, *pw2lo, *pa2hi, *pa2lo;
    cudaGetSymbolAddress((void**)&pH, g_h16);
    cudaGetSymbolAddress((void**)&pw1hi, g_w1hi);
    cudaGetSymbolAddress((void**)&pw1lo, g_w1lo);
    cudaGetSymbolAddress((void**)&pw2hi, g_w2hi);
    cudaGetSymbolAddress((void**)&pw2lo, g_w2lo);
    cudaGetSymbolAddress((void**)&pa2hi, g_a2hi);
    cudaGetSymbolAddress((void**)&pa2lo, g_a2lo);
    __half2* pH2 = reinterpret_cast<__half2*>(pH);

    static cudaStream_t s2 = nullptr;
    static cudaEvent_t evFork = nullptr, evJoin = nullptr;
    if (!s2) {
        cudaStreamCreateWithFlags(&s2, cudaStreamNonBlocking);
        cudaEventCreateWithFlags(&evFork, cudaEventDisableTiming);
        cudaEventCreateWithFlags(&evJoin, cudaEventDisableTiming);
    }

    cudaEventRecord(evFork, 0);
    cudaStreamWaitEvent(s2, evFork, 0);

    k_split<<<25, 256>>>((const float4*)w1, (uint4*)pw1hi, (uint4*)pw1lo,
                         F_IN * F_HID / 8);
    k_split<<<8, 256>>>((const float4*)w2, (uint4*)pw2hi, (uint4*)pw2lo,
                        F_HID * F_HID / 8);
    k_init_dc<<<(N_NODES + 255) / 256, 256, 0, s2>>>();
    k_gemm_a32<<<N_NODES / 128, 256>>>(x, pw1hi, pw1lo, pH, F_IN);
    k_edge_pass1<<<(N_EDGES / 4 + 255) / 256, 256, 0, s2>>>(col, ea);
    k_part_dinv<<<SCAN_BLOCKS, 1024, 0, s2>>>();
    k_scan_part<<<1, 32, 0, s2>>>();
    k_scan_blocks<<<SCAN_BLOCKS, 1024, 0, s2>>>();
    k_edge_pass2<<<(N_EDGES / 4 + 255) / 256, 256, 0, s2>>>(row, col, ea);
    cudaEventRecord(evJoin, s2);

    cudaStreamWaitEvent(0, evJoin, 0);

    k_agg1<<<N_NODES, 64>>>(pH2, b1, (__nv_bfloat162*)pa2hi, (__nv_bfloat162*)pa2lo);
    k_gemm_ps<<<N_NODES / 128, 256>>>(pa2hi, pa2lo, pw2hi, pw2lo, pH, F_HID);
    k_agg2ro<<<N_NODES, 64>>>(pH2, b2, ro_w, ro_b);

    k_fc1<<<N_GRAPHS * NCHUNKS, FC1_OUT>>>(fc1_w);
    k_zred<<<(N_GRAPHS * FC1_OUT + 255) / 256, 256>>>(fc1_b);
    k_head<<<N_GRAPHS, 512>>>(gamma, beta, fc2_w, fc2_b, out);
}